// round 3
// baseline (speedup 1.0000x reference)
#include <cuda_runtime.h>
#include <cstdint>

// Problem constants (fixed by the reference)
#define NN      2048
#define DF      512
#define MSUP    512
#define NPAIRS  2096128       // N*(N-1)/2
#define TARGET  1536          // N - NUM_SUPER merges
#define MAXDEG  512

// rank table: inter in [0,64), union in [0,128)
#define TI      64
#define TU      128
#define NCOMB   (TI*TU)       // 8192
#define SPLIT   16            // idx>>18 gives 4 bits
#define NSB     (NCOMB*SPLIT) // 131072 sub-buckets

// Output layout: X_coarse [512,512] | A_coarse [512,512] | P [2048,512]
#define XC_OFF  0
#define AC_OFF  262144
#define P_OFF   524288
#define OUT_N   1572864

// -------- scratch (device globals; no allocation allowed) --------
__device__ int      g_adj[NN * MAXDEG];    // 4 MB
__device__ int      g_deg[NN];
__device__ int      g_inter[NN * NN];      // 16 MB (upper triangle)
__device__ unsigned g_rank[NCOMB];         // 13-bit rank per (inter,union)
__device__ unsigned g_hist[NSB];           // 512 KB
__device__ unsigned g_off[NSB];            // scatter cursors
__device__ unsigned g_basearr[NSB];        // exclusive-scan bases
__device__ unsigned g_posidx[NPAIRS];      // scattered positive pair indices
__device__ unsigned g_sbbase[NSB];         // compacted non-empty buckets: base
__device__ unsigned g_sbsize[NSB];         //                              size
__device__ int      g_nsb;
__device__ int      g_labels[NN];
__device__ float    g_wnode[NN];

// -------- 1) adjacency lists + degrees (warp per row, ascending j) --------
__global__ void k_adj(const float* __restrict__ A) {
    int warp = (blockIdx.x * blockDim.x + threadIdx.x) >> 5;
    int lane = threadIdx.x & 31;
    if (warp >= NN) return;
    const float* row = A + (size_t)warp * NN;
    int cnt = 0;
    for (int k = 0; k < NN; k += 32) {
        float v = row[k + lane];
        unsigned b = __ballot_sync(0xFFFFFFFFu, v > 0.0f);
        if (v > 0.0f) {
            int pos = cnt + __popc(b & ((1u << lane) - 1u));
            if (pos < MAXDEG) g_adj[warp * MAXDEG + pos] = k + lane;
        }
        cnt += __popc(b);
    }
    if (lane == 0) g_deg[warp] = cnt;
}

// -------- 2) zero scratch (inter matrix + histograms + cursors) --------
__global__ void k_zeroscratch() {
    size_t t = (size_t)blockIdx.x * blockDim.x + threadIdx.x;
    size_t stride = (size_t)gridDim.x * blockDim.x;
    int4 z = make_int4(0, 0, 0, 0);
    for (size_t i = t; i < (size_t)NN * NN / 4; i += stride)
        reinterpret_cast<int4*>(g_inter)[i] = z;
    for (size_t i = t; i < NSB / 4; i += stride) {
        reinterpret_cast<int4*>(g_hist)[i] = z;
        reinterpret_cast<int4*>(g_off)[i] = z;
    }
}

// -------- 3) sparse triangle counting --------
__global__ void k_tri() {
    int warp = (blockIdx.x * blockDim.x + threadIdx.x) >> 5;
    int lane = threadIdx.x & 31;
    if (warp >= NN) return;
    int d = min(g_deg[warp], MAXDEG);
    const int* nb = &g_adj[warp * MAXDEG];
    for (int a = 0; a < d - 1; a++) {
        int i = nb[a];                    // ascending => i < j below
        int* irow = &g_inter[i * NN];
        for (int b = a + 1 + lane; b < d; b += 32)
            atomicAdd(&irow[nb[b]], 1);
    }
}

// -------- 4) rank table: monotone 13-bit rank of every possible jaccard --------
// rank 0 = highest similarity. Equal floats share a rank (upper_bound trick).
__global__ void k_tbl() {
    __shared__ unsigned arr[NCOMB];       // 32 KB
    int tid = threadIdx.x;
    for (int c = tid; c < NCOMB; c += 1024) {
        int i = c >> 7, u = c & (TU - 1);
        float jac = (u == 0) ? 0.0f : __fdiv_rn((float)i, (float)u);
        arr[c] = __float_as_uint(jac);    // jac >= +0 => bits monotone in value
    }
    __syncthreads();
    // bitonic ascending over 8192
    for (int k = 2; k <= NCOMB; k <<= 1)
        for (int j = k >> 1; j > 0; j >>= 1) {
            for (int t = tid; t < NCOMB; t += 1024) {
                int x = t ^ j;
                if (x > t) {
                    unsigned a = arr[t], b = arr[x];
                    if (((t & k) == 0) ? (a > b) : (a < b)) { arr[t] = b; arr[x] = a; }
                }
            }
            __syncthreads();
        }
    // rank = NCOMB - upper_bound(arr, fb)
    for (int c = tid; c < NCOMB; c += 1024) {
        int i = c >> 7, u = c & (TU - 1);
        float jac = (u == 0) ? 0.0f : __fdiv_rn((float)i, (float)u);
        unsigned fb = __float_as_uint(jac);
        int lo = 0, hi = NCOMB;           // first index with arr[idx] > fb
        while (lo < hi) { int m = (lo + hi) >> 1; if (arr[m] <= fb) lo = m + 1; else hi = m; }
        g_rank[c] = (unsigned)(NCOMB - lo);
    }
}

// -------- 5) count positives per sub-bucket --------
__device__ __forceinline__ unsigned sbid_of(int inter, int uni, unsigned idx) {
    int ic = min(inter, TI - 1), uc = min(uni, TU - 1);
    return g_rank[ic * TU + uc] * SPLIT + (idx >> 18);
}

__global__ void k_count() {
    __shared__ int sdeg[NN];
    int i = blockIdx.x;
    for (int t = threadIdx.x; t < NN; t += blockDim.x) sdeg[t] = g_deg[t];
    __syncthreads();
    if (i >= NN - 1) return;
    int di = sdeg[i];
    const int* irow = &g_inter[i * NN];
    for (int j = i + 1 + threadIdx.x; j < NN; j += blockDim.x) {
        int inter = irow[j];
        if (inter > 0) {
            unsigned idx = (unsigned)(i * NN + j);
            atomicAdd(&g_hist[sbid_of(inter, di + sdeg[j] - inter, idx)], 1u);
        }
    }
}

// -------- 6) scan: bases + compact non-empty sub-bucket list (in order) --------
__global__ void k_scan() {
    __shared__ unsigned tsum[1024], tcnt[1024];
    int tid = threadIdx.x;
    const int PER = NSB / 1024;           // 128
    unsigned s = 0, c = 0;
    for (int k = 0; k < PER; k++) {
        unsigned v = g_hist[tid * PER + k];
        s += v; c += (v > 0);
    }
    tsum[tid] = s; tcnt[tid] = c;
    __syncthreads();
    // Hillis-Steele inclusive scans
    for (int d = 1; d < 1024; d <<= 1) {
        unsigned a = (tid >= d) ? tsum[tid - d] : 0u;
        unsigned b = (tid >= d) ? tcnt[tid - d] : 0u;
        __syncthreads();
        tsum[tid] += a; tcnt[tid] += b;
        __syncthreads();
    }
    unsigned base = tsum[tid] - s;        // exclusive
    unsigned pos = tcnt[tid] - c;
    for (int k = 0; k < PER; k++) {
        int sb = tid * PER + k;
        unsigned v = g_hist[sb];
        g_basearr[sb] = base;
        if (v > 0) { g_sbbase[pos] = base; g_sbsize[pos] = v; pos++; }
        base += v;
    }
    if (tid == 1023) g_nsb = (int)tcnt[1023];
}

// -------- 7) scatter positive pair indices into sub-buckets --------
// (order within a sub-bucket is nondeterministic; k_uf re-sorts by index)
__global__ void k_scatter() {
    __shared__ int sdeg[NN];
    int i = blockIdx.x;
    for (int t = threadIdx.x; t < NN; t += blockDim.x) sdeg[t] = g_deg[t];
    __syncthreads();
    if (i >= NN - 1) return;
    int di = sdeg[i];
    const int* irow = &g_inter[i * NN];
    for (int j = i + 1 + threadIdx.x; j < NN; j += blockDim.x) {
        int inter = irow[j];
        if (inter > 0) {
            unsigned idx = (unsigned)(i * NN + j);
            unsigned sb = sbid_of(inter, di + sdeg[j] - inter, idx);
            unsigned slot = atomicAdd(&g_off[sb], 1u);
            g_posidx[g_basearr[sb] + slot] = idx;
        }
    }
}

// -------- 8) union-find over sub-buckets in rank order --------
__global__ void k_uf() {
    __shared__ int parent[NN];
    __shared__ int lor[NN];
    __shared__ int ssz[MSUP];
    __shared__ float swc[MSUP];
    __shared__ unsigned slist[8192];      // 32 KB
    __shared__ unsigned cidx[1024];
    __shared__ int scnt[32], soff[33];
    __shared__ int s_done, s_merged;
    int tid = threadIdx.x, lane = tid & 31, w = tid >> 5;

    for (int t = tid; t < NN; t += 1024) { parent[t] = t; lor[t] = -1; }
    for (int t = tid; t < MSUP; t += 1024) ssz[t] = 0;
    if (tid == 0) { s_done = 0; s_merged = 0; }
    __syncthreads();

    int nsb = g_nsb;
    for (int q = 0; q < nsb && !s_done; q++) {
        unsigned bbase = g_sbbase[q];
        int s = (int)g_sbsize[q];
        for (int ch = 0; ch < s && !s_done; ch += 8192) {
            int cs = min(8192, s - ch);
            int n2 = 32; while (n2 < cs) n2 <<= 1;
            for (int t = tid; t < n2; t += 1024)
                slist[t] = (t < cs) ? g_posidx[bbase + ch + t] : 0xFFFFFFFFu;
            __syncthreads();
            // bitonic ascending by pair index (restores exact stable order)
            for (int k = 2; k <= n2; k <<= 1)
                for (int j = k >> 1; j > 0; j >>= 1) {
                    for (int t = tid; t < n2; t += 1024) {
                        int x = t ^ j;
                        if (x > t) {
                            unsigned a = slist[t], b = slist[x];
                            if (((t & k) == 0) ? (a > b) : (a < b)) { slist[t] = b; slist[x] = a; }
                        }
                    }
                    __syncthreads();
                }
            // consume in 1024-sized rounds: parallel reject + serial merge
            for (int off = 0; off < cs; off += 1024) {
                bool cand = false; unsigned idx = 0;
                if (off + tid < cs) {
                    idx = slist[off + tid];
                    int i = idx >> 11, j = idx & (NN - 1);
                    int ri = i; while (parent[ri] != ri) ri = parent[ri];
                    int rj = j; while (parent[rj] != rj) rj = parent[rj];
                    cand = (ri != rj);
                }
                unsigned b = __ballot_sync(0xFFFFFFFFu, cand);
                if (lane == 0) scnt[w] = __popc(b);
                __syncthreads();
                if (tid == 0) {
                    int acc = 0;
                    #pragma unroll
                    for (int k2 = 0; k2 < 32; k2++) { soff[k2] = acc; acc += scnt[k2]; }
                    soff[32] = acc;
                }
                __syncthreads();
                if (cand) cidx[soff[w] + __popc(b & ((1u << lane) - 1u))] = idx;
                __syncthreads();
                if (tid == 0) {
                    int nc = soff[32];
                    for (int c = 0; c < nc; c++) {
                        unsigned id = cidx[c];
                        int a = id >> 11, bb = id & (NN - 1);
                        int ra = a;  while (parent[ra] != ra) { parent[ra] = parent[parent[ra]]; ra = parent[ra]; }
                        int rb = bb; while (parent[rb] != rb) { parent[rb] = parent[parent[rb]]; rb = parent[rb]; }
                        if (ra != rb) {
                            parent[rb] = ra;
                            if (++s_merged == TARGET) { s_done = 1; break; }
                        }
                    }
                }
                __syncthreads();
                if (s_done) break;
            }
        }
    }

    // zero-jaccard fallback: natural index order, skipping positives
    if (!s_done) {
        for (int i = 0; i < NN - 1 && !s_done; i++) {
            const int* irow = &g_inter[i * NN];
            for (int jb = i + 1; jb < NN && !s_done; jb += 1024) {
                int j = jb + tid;
                bool cand = false;
                if (j < NN && irow[j] == 0) {
                    int ri = i; while (parent[ri] != ri) ri = parent[ri];
                    int rj = j; while (parent[rj] != rj) rj = parent[rj];
                    cand = (ri != rj);
                }
                unsigned b = __ballot_sync(0xFFFFFFFFu, cand);
                if (lane == 0) scnt[w] = __popc(b);
                __syncthreads();
                if (tid == 0) {
                    int acc = 0;
                    #pragma unroll
                    for (int k2 = 0; k2 < 32; k2++) { soff[k2] = acc; acc += scnt[k2]; }
                    soff[32] = acc;
                }
                __syncthreads();
                if (cand) cidx[soff[w] + __popc(b & ((1u << lane) - 1u))] = (unsigned)(i * NN + j);
                __syncthreads();
                if (tid == 0) {
                    int nc = soff[32];
                    for (int c = 0; c < nc; c++) {
                        unsigned id = cidx[c];
                        int a = id >> 11, bb = id & (NN - 1);
                        int ra = a;  while (parent[ra] != ra) { parent[ra] = parent[parent[ra]]; ra = parent[ra]; }
                        int rb = bb; while (parent[rb] != rb) { parent[rb] = parent[parent[rb]]; rb = parent[rb]; }
                        if (ra != rb) {
                            parent[rb] = ra;
                            if (++s_merged == TARGET) { s_done = 1; break; }
                        }
                    }
                }
                __syncthreads();
            }
        }
    }
    __syncthreads();

    // labeling: rank of component's minimum node index
    if (tid == 0) {
        int next = 0;
        for (int i = 0; i < NN; i++) {
            int r = i; while (parent[r] != r) { parent[r] = parent[parent[r]]; r = parent[r]; }
            int l = lor[r];
            if (l < 0) { l = next++; lor[r] = l; }
            g_labels[i] = l;
            ssz[l]++;
        }
    }
    __syncthreads();
    for (int t = tid; t < MSUP; t += 1024)
        swc[t] = 1.0f / sqrtf((float)ssz[t] + 1e-10f);
    __syncthreads();
    for (int t = tid; t < NN; t += 1024)
        g_wnode[t] = swc[g_labels[t]];
}

// -------- 9) epilogue --------
__global__ void k_zero(float* out) {
    int t = blockIdx.x * blockDim.x + threadIdx.x;
    float4 z = make_float4(0.f, 0.f, 0.f, 0.f);
    for (int i = t; i < OUT_N / 4; i += gridDim.x * blockDim.x)
        reinterpret_cast<float4*>(out)[i] = z;
}

__global__ void k_fill_P(float* out) {
    int i = blockIdx.x * blockDim.x + threadIdx.x;
    if (i < NN) out[P_OFF + i * MSUP + g_labels[i]] = g_wnode[i];
}

__global__ void k_xcoarse(const float* __restrict__ X, float* out) {
    int t = blockIdx.x * blockDim.x + threadIdx.x;
    if (t < NN * DF) {
        int i = t >> 9, d = t & (DF - 1);
        atomicAdd(&out[XC_OFF + g_labels[i] * DF + d], g_wnode[i] * X[t]);
    }
}

__global__ void k_acoarse(const float* __restrict__ A, float* out) {
    int warp = (blockIdx.x * blockDim.x + threadIdx.x) >> 5;
    int lane = threadIdx.x & 31;
    if (warp >= NN) return;
    int i = warp;
    int d = min(g_deg[i], MAXDEG);
    float wi = g_wnode[i];
    int li = g_labels[i];
    for (int a = lane; a < d; a += 32) {
        int j = g_adj[i * MAXDEG + a];
        float v = A[(size_t)i * NN + j];
        atomicAdd(&out[AC_OFF + li * MSUP + g_labels[j]], wi * g_wnode[j] * v);
    }
}

// -------- launch --------
extern "C" void kernel_launch(void* const* d_in, const int* in_sizes, int n_in,
                              void* d_out, int out_size) {
    const float* X = (const float*)d_in[0];
    const float* A = (const float*)d_in[1];
    float* out = (float*)d_out;

    k_adj<<<NN / 8, 256>>>(A);
    k_zeroscratch<<<256, 256>>>();
    k_tbl<<<1, 1024>>>();
    k_tri<<<NN / 8, 256>>>();
    k_count<<<NN, 256>>>();
    k_scan<<<1, 1024>>>();
    k_scatter<<<NN, 256>>>();
    k_uf<<<1, 1024>>>();

    k_zero<<<256, 256>>>(out);
    k_fill_P<<<NN / 256, 256>>>(out);
    k_xcoarse<<<(NN * DF) / 256, 256>>>(X, out);
    k_acoarse<<<NN / 8, 256>>>(A, out);
}